// round 10
// baseline (speedup 1.0000x reference)
#include <cuda_runtime.h>
#include <cuda_bf16.h>
#include <cstdint>

#define N_ROWS 10000
#define DIM    256
#define NB     79            // ceil(10000/128)
#define NPAD   (NB * 128)    // 10112
#define LDOUT  10000
#define LDADJ  10016         // bf16 scratch row pitch (mult of 8; 16B-aligned rows)
#define CAND_MAX 1024
#define DELTA  2e-2f

// ---------------- scratch (static device globals: allocation-free) ----------
__device__ float g_x1[NPAD * DIM];
__device__ float g_e [NPAD * DIM];
__device__ __nv_bfloat16 g_ehi[NPAD * DIM];
__device__ __nv_bfloat16 g_adj[(size_t)N_ROWS * LDADJ];   // ~200 MB approx adj

// ================= helpers =================
__device__ __forceinline__ uint32_t smem_u32(const void* p) {
    uint32_t a;
    asm("{ .reg .u64 t; cvta.to.shared.u64 t, %1; cvt.u32.u64 %0, t; }" : "=r"(a) : "l"(p));
    return a;
}
__device__ __forceinline__ void cp16(uint32_t dst, const void* src) {
    asm volatile("cp.async.cg.shared.global [%0], [%1], 16;" :: "r"(dst), "l"(src));
}
#define CP_COMMIT() asm volatile("cp.async.commit_group;")
#define CP_WAIT0()  asm volatile("cp.async.wait_group 0;")

__device__ __forceinline__ void ldm_x4(uint32_t& r0, uint32_t& r1, uint32_t& r2, uint32_t& r3,
                                       uint32_t addr) {
    asm volatile("ldmatrix.sync.aligned.m8n8.x4.shared.b16 {%0,%1,%2,%3}, [%4];"
                 : "=r"(r0), "=r"(r1), "=r"(r2), "=r"(r3) : "r"(addr));
}
__device__ __forceinline__ void ldm_x2(uint32_t& r0, uint32_t& r1, uint32_t addr) {
    asm volatile("ldmatrix.sync.aligned.m8n8.x2.shared.b16 {%0,%1}, [%2];"
                 : "=r"(r0), "=r"(r1) : "r"(addr));
}
__device__ __forceinline__ void mma_bf16(float* c, const uint32_t* a, const uint32_t* b) {
    asm volatile("mma.sync.aligned.m16n8k16.row.col.f32.bf16.bf16.f32 "
                 "{%0,%1,%2,%3}, {%4,%5,%6,%7}, {%8,%9}, {%0,%1,%2,%3};"
                 : "+f"(c[0]), "+f"(c[1]), "+f"(c[2]), "+f"(c[3])
                 : "r"(a[0]), "r"(a[1]), "r"(a[2]), "r"(a[3]), "r"(b[0]), "r"(b[1]));
}
__device__ __forceinline__ uint32_t pack_bf2(float lo, float hi) {
    __nv_bfloat162 b;
    b.x = __float2bfloat16(lo);
    b.y = __float2bfloat16(hi);
    return *reinterpret_cast<uint32_t*>(&b);
}

// ---------------- shared GEMM core: C = act(A @ W^T + bias) -----------------
template<bool RELU, bool GUARD_A>
__device__ __forceinline__ void mlp_gemm_core(const float* __restrict__ A,
                                              const float* __restrict__ W,
                                              const float* __restrict__ bias,
                                              float* __restrict__ C, int mreal)
{
    __shared__ float As[16][128];
    __shared__ float Bs[16][128];
    const int tid  = threadIdx.x;
    const int tx   = tid & 15, ty = tid >> 4;
    const int row0 = ty * 8, col0 = tx * 8;
    const int br = blockIdx.x, bc = blockIdx.y;

    float c[8][8];
#pragma unroll
    for (int i = 0; i < 8; i++)
#pragma unroll
        for (int j = 0; j < 8; j++) c[i][j] = 0.f;

    for (int k0 = 0; k0 < DIM; k0 += 16) {
#pragma unroll
        for (int l = 0; l < 2; l++) {
            int idx = tid * 2 + l;
            int r   = idx >> 2;
            int c4  = (idx & 3) * 4;
            int arow = br * 128 + r;
            float4 v;
            if (!GUARD_A || arow < mreal)
                v = *reinterpret_cast<const float4*>(&A[(long)arow * DIM + k0 + c4]);
            else
                v = make_float4(0.f, 0.f, 0.f, 0.f);
            As[c4 + 0][r] = v.x; As[c4 + 1][r] = v.y;
            As[c4 + 2][r] = v.z; As[c4 + 3][r] = v.w;
            int wrow = bc * 128 + r;
            float4 w = *reinterpret_cast<const float4*>(&W[(long)wrow * DIM + k0 + c4]);
            Bs[c4 + 0][r] = w.x; Bs[c4 + 1][r] = w.y;
            Bs[c4 + 2][r] = w.z; Bs[c4 + 3][r] = w.w;
        }
        __syncthreads();
#pragma unroll
        for (int k = 0; k < 16; k++) {
            float a[8], b[8];
            *(float4*)&a[0] = *(const float4*)&As[k][row0];
            *(float4*)&a[4] = *(const float4*)&As[k][row0 + 4];
            *(float4*)&b[0] = *(const float4*)&Bs[k][col0];
            *(float4*)&b[4] = *(const float4*)&Bs[k][col0 + 4];
#pragma unroll
            for (int i = 0; i < 8; i++)
#pragma unroll
                for (int j = 0; j < 8; j++)
                    c[i][j] = fmaf(a[i], b[j], c[i][j]);
        }
        __syncthreads();
    }
#pragma unroll
    for (int i = 0; i < 8; i++) {
        int grow = br * 128 + row0 + i;
#pragma unroll
        for (int j = 0; j < 8; j++) {
            int gcol = bc * 128 + col0 + j;
            float v = c[i][j] + bias[gcol];
            if (RELU) v = fmaxf(v, 0.f);
            C[(long)grow * DIM + gcol] = v;
        }
    }
}

__global__ void mlp1_kernel(const float* __restrict__ h,
                            const float* __restrict__ W1,
                            const float* __restrict__ b1)
{
    mlp_gemm_core<true, true>(h, W1, b1, g_x1, N_ROWS);
}

__global__ void mlp2_kernel(const float* __restrict__ W2,
                            const float* __restrict__ b2)
{
    mlp_gemm_core<false, false>(g_x1, W2, b2, g_e, N_ROWS);
}

// -------- row L2-normalize; emit fp32 e and bf16; zero pads -----------------
__global__ void normalize_kernel()
{
    const int row = blockIdx.x;
    const int tid = threadIdx.x;           // 256 == DIM
    float v = g_e[(long)row * DIM + tid];
    float s = v * v;
#pragma unroll
    for (int off = 16; off > 0; off >>= 1)
        s += __shfl_xor_sync(0xffffffffu, s, off);
    __shared__ float warpsum[8];
    if ((tid & 31) == 0) warpsum[tid >> 5] = s;
    __syncthreads();
    float tot = 0.f;
#pragma unroll
    for (int w = 0; w < 8; w++) tot += warpsum[w];
    float denom = fmaxf(sqrtf(tot), 1e-12f);
    float e = (row < N_ROWS) ? v / denom : 0.f;
    g_e[(long)row * DIM + tid] = e;
    g_ehi[(long)row * DIM + tid] = __float2bfloat16(e);
}

// ---------------- approx adj via mma.sync bf16 -> bf16 scratch --------------
#define KT    32
#define APAD  40                         // row pitch in bf16 elems (80 B)
#define MATB  (128 * APAD * 2)           // 10240 B per matrix buffer
#define BUFB  (2 * MATB)                 // A+B per buffer
#define NCHUNK 8                         // 256 / 32

__global__ void __launch_bounds__(256, 2) adj_hmma_kernel()
{
    const int bc = blockIdx.x, br = blockIdx.y;
    if (bc < br) return;

    __shared__ __align__(16) char smem_raw[2 * BUFB];   // 40960 B
    const uint32_t sb = smem_u32(smem_raw);

    const int tid  = threadIdx.x;
    const int wid  = tid >> 5, lane = tid & 31;
    const int warp_m = wid >> 2, warp_n = wid & 3;      // 2 x 4 warp grid

    float acc[4][4][4];
#pragma unroll
    for (int mi = 0; mi < 4; mi++)
#pragma unroll
        for (int ni = 0; ni < 4; ni++)
#pragma unroll
            for (int q = 0; q < 4; q++) acc[mi][ni][q] = 0.f;

    const size_t aBase = (size_t)(br * 128) * DIM;
    const size_t bBase = (size_t)(bc * 128) * DIM;

    const int u0r = tid >> 2,         u0c = (tid & 3) * 16;
    const int u1r = (tid + 256) >> 2, u1c = u0c;

    auto issue = [&](int chunk, int buf) {
        const int kk = chunk * KT;
        const char* gA = (const char*)(g_ehi + aBase + kk);
        const char* gB = (const char*)(g_ehi + bBase + kk);
        uint32_t dA = sb + buf * BUFB;
        uint32_t dB = dA + MATB;
        cp16(dA + u0r * 80 + u0c, gA + (size_t)u0r * (DIM * 2) + u0c);
        cp16(dA + u1r * 80 + u1c, gA + (size_t)u1r * (DIM * 2) + u1c);
        cp16(dB + u0r * 80 + u0c, gB + (size_t)u0r * (DIM * 2) + u0c);
        cp16(dB + u1r * 80 + u1c, gB + (size_t)u1r * (DIM * 2) + u1c);
    };

    const uint32_t aAddr0 = sb + ((warp_m * 64 + (lane & 15)) * APAD) * 2 + (lane >> 4) * 16;
    const uint32_t bAddr0 = sb + MATB + ((warp_n * 32 + (lane & 7)) * APAD) * 2
                               + ((lane >> 3) & 1) * 16;

    issue(0, 0); CP_COMMIT(); CP_WAIT0(); __syncthreads();

#pragma unroll
    for (int c = 0; c < NCHUNK; ++c) {
        const int buf = c & 1;
        if (c + 1 < NCHUNK) { issue(c + 1, buf ^ 1); CP_COMMIT(); }

        const uint32_t aB = aAddr0 + buf * BUFB;
        const uint32_t bB = bAddr0 + buf * BUFB;
#pragma unroll
        for (int ks = 0; ks < 2; ++ks) {
            uint32_t afr[4][4], bfr[4][2];
#pragma unroll
            for (int mi = 0; mi < 4; mi++)
                ldm_x4(afr[mi][0], afr[mi][1], afr[mi][2], afr[mi][3],
                       aB + mi * (16 * APAD * 2) + ks * 32);
#pragma unroll
            for (int ni = 0; ni < 4; ni++)
                ldm_x2(bfr[ni][0], bfr[ni][1],
                       bB + ni * (8 * APAD * 2) + ks * 32);
#pragma unroll
            for (int mi = 0; mi < 4; mi++)
#pragma unroll
                for (int ni = 0; ni < 4; ni++)
                    mma_bf16(acc[mi][ni], afr[mi], bfr[ni]);
        }
        if (c + 1 < NCHUNK) { CP_WAIT0(); __syncthreads(); }
    }

    // ---- direct store of upper tile (bf16 pairs) ----
#pragma unroll
    for (int mi = 0; mi < 4; mi++) {
        const int r0 = br * 128 + warp_m * 64 + mi * 16 + (lane >> 2);
#pragma unroll
        for (int ni = 0; ni < 4; ni++) {
            const int gc = bc * 128 + warp_n * 32 + ni * 8 + (lane & 3) * 2;
            if (gc < N_ROWS) {
                if (r0 < N_ROWS)
                    *reinterpret_cast<uint32_t*>(&g_adj[(size_t)r0 * LDADJ + gc]) =
                        pack_bf2(acc[mi][ni][0], acc[mi][ni][1]);
                if (r0 + 8 < N_ROWS)
                    *reinterpret_cast<uint32_t*>(&g_adj[(size_t)(r0 + 8) * LDADJ + gc]) =
                        pack_bf2(acc[mi][ni][2], acc[mi][ni][3]);
            }
        }
    }

    // ---- mirrored store via smem transpose (skip diagonal), bf16 ----
    if (br != bc) {
        float* Tf = reinterpret_cast<float*>(smem_raw);   // [128 cols][68 rows]
#pragma unroll
        for (int h = 0; h < 2; ++h) {
            __syncthreads();
            if (warp_m == h) {
#pragma unroll
                for (int mi = 0; mi < 4; mi++) {
                    const int rl = mi * 16 + (lane >> 2);
#pragma unroll
                    for (int ni = 0; ni < 4; ni++) {
                        const int cl = warp_n * 32 + ni * 8 + (lane & 3) * 2;
                        Tf[cl * 68 + rl]           = acc[mi][ni][0];
                        Tf[(cl + 1) * 68 + rl]     = acc[mi][ni][1];
                        Tf[cl * 68 + rl + 8]       = acc[mi][ni][2];
                        Tf[(cl + 1) * 68 + rl + 8] = acc[mi][ni][3];
                    }
                }
            }
            __syncthreads();
#pragma unroll
            for (int p = 0; p < 8; ++p) {
                const int idx = tid + p * 256;
                const int i = idx >> 4;              // local mirror row (orig col)
                const int j = idx & 15;              // 4-float group
                const int grow2 = bc * 128 + i;
                if (grow2 < N_ROWS) {
                    // cols = br*128 + h*64 + j*4 ; br <= 77 here -> always < N_ROWS
                    uint2 pk;
                    pk.x = pack_bf2(Tf[i * 68 + j * 4 + 0], Tf[i * 68 + j * 4 + 1]);
                    pk.y = pack_bf2(Tf[i * 68 + j * 4 + 2], Tf[i * 68 + j * 4 + 3]);
                    *reinterpret_cast<uint2*>(
                        &g_adj[(size_t)grow2 * LDADJ + br * 128 + h * 64 + j * 4]) = pk;
                }
            }
        }
    }
}

// ---- fused select: 13-bit radix threshold + margin collect + exact rescore -
__device__ __forceinline__ unsigned fkey(float f)
{
    unsigned u = __float_as_uint(f);
    return (u & 0x80000000u) ? ~u : (u | 0x80000000u);
}
__device__ __forceinline__ float kinv(unsigned key)
{
    unsigned u = (key & 0x80000000u) ? (key & 0x7fffffffu) : ~key;
    return __uint_as_float(u);
}

#define NBINS 8192    // 13-bit: sign + 8 exp + 4 mantissa

__global__ void select_kernel(float* __restrict__ out, const int* __restrict__ kp)
{
    __shared__ unsigned hist[NBINS];
    __shared__ unsigned chunkSum[256];
    __shared__ float erow[DIM];
    __shared__ float cval[CAND_MAX];
    __shared__ int   cidx[CAND_MAX];
    __shared__ int candCnt;
    __shared__ unsigned sh_b1;

    const int row = blockIdx.x;
    const int tid = threadIdx.x;
    const uint4* a4 = reinterpret_cast<const uint4*>(g_adj + (size_t)row * LDADJ);
    float* rowp = out + (long)row * LDOUT;
    const unsigned K1 = (unsigned)(kp[0] + 1);

    for (int i = tid; i < NBINS; i += 256) hist[i] = 0;
    if (tid == 0) candCnt = 0;
    erow[tid] = g_e[(long)row * DIM + tid];
    __syncthreads();

    // ---- pass 1: 13-bit histogram over 10000 bf16 (1250 uint4 loads) ----
    for (int i = tid; i < LDOUT / 8; i += 256) {
        uint4 u = a4[i];
        const uint32_t* w = &u.x;
#pragma unroll
        for (int q = 0; q < 4; ++q) {
            float2 f = __bfloat1622float2(*reinterpret_cast<const __nv_bfloat162*>(&w[q]));
            atomicAdd(&hist[fkey(f.x) >> 19], 1u);
            atomicAdd(&hist[fkey(f.y) >> 19], 1u);
        }
    }
    __syncthreads();
    {
        unsigned s = 0;
#pragma unroll
        for (int b = 0; b < 32; b++) s += hist[tid * 32 + b];
        chunkSum[tid] = s;
    }
    __syncthreads();
    if (tid == 0) {
        unsigned cum = 0;
        sh_b1 = 0;
        for (int t = 255; t >= 0; --t) {
            if (cum + chunkSum[t] >= K1) {
                for (int b = t * 32 + 31; b >= t * 32; --b) {
                    unsigned hh = hist[b];
                    if (cum + hh >= K1) { sh_b1 = (unsigned)b; break; }
                    cum += hh;
                }
                break;
            }
            cum += chunkSum[t];
        }
    }
    __syncthreads();

    // threshold = bin floor - margin (covers bf16 GEMM + storage error)
    const float TmF = kinv(sh_b1 << 19) - DELTA;

    // ---- pass 2: collect candidates (L2 re-read) ----
    for (int i = tid; i < LDOUT / 8; i += 256) {
        uint4 u = a4[i];
        const uint32_t* w = &u.x;
#pragma unroll
        for (int q = 0; q < 4; ++q) {
            float2 f = __bfloat1622float2(*reinterpret_cast<const __nv_bfloat162*>(&w[q]));
            if (f.x >= TmF) {
                int p = atomicAdd(&candCnt, 1);
                if (p < CAND_MAX) cidx[p] = i * 8 + q * 2;
            }
            if (f.y >= TmF) {
                int p = atomicAdd(&candCnt, 1);
                if (p < CAND_MAX) cidx[p] = i * 8 + q * 2 + 1;
            }
        }
    }
    // stream zeros into the output row (independent of collection)
    {
        float4* o4 = reinterpret_cast<float4*>(rowp);
        const float4 z = make_float4(0.f, 0.f, 0.f, 0.f);
        for (int i = tid; i < LDOUT / 4; i += 256) o4[i] = z;
    }
    __syncthreads();
    const int n = candCnt < CAND_MAX ? candCnt : CAND_MAX;

    // ---- exact fp32 rescore ----
    for (int c = tid; c < n; c += 256) {
        const float* ec = &g_e[(long)cidx[c] * DIM];
        float a = 0.f;
#pragma unroll 8
        for (int k = 0; k < DIM; ++k) a = fmaf(erow[k], ec[k], a);
        cval[c] = a;
    }
    __syncthreads();

    // ---- rank (val desc, idx asc) and scatter kept entries ----
    for (int c = tid; c < n; c += 256) {
        float v = cval[c];
        int  id = cidx[c];
        int rank = 0;
        for (int o = 0; o < n; ++o) {
            float vo = cval[o];
            rank += (vo > v) || (vo == v && cidx[o] < id);
        }
        if (rank < (int)K1) rowp[id] = fmaxf(v, 0.f);
    }
}

// ---------------- launch ----------------------------------------------------
extern "C" void kernel_launch(void* const* d_in, const int* in_sizes, int n_in,
                              void* d_out, int out_size)
{
    const float* h  = (const float*)d_in[0];
    const float* W1 = (const float*)d_in[1];
    const float* b1 = (const float*)d_in[2];
    const float* W2 = (const float*)d_in[3];
    const float* b2 = (const float*)d_in[4];
    const int*   kp = (const int*)  d_in[5];
    float* out = (float*)d_out;

    mlp1_kernel<<<dim3(NB, 2), 256>>>(h, W1, b1);
    mlp2_kernel<<<dim3(NB, 2), 256>>>(W2, b2);
    normalize_kernel<<<NPAD, 256>>>();
    adj_hmma_kernel<<<dim3(NB, NB), 256>>>();
    select_kernel<<<N_ROWS, 256>>>(out, kp);
}

// round 11
// speedup vs baseline: 1.3583x; 1.3583x over previous
#include <cuda_runtime.h>
#include <cuda_bf16.h>
#include <cstdint>

#define N_ROWS 10000
#define DIM    256
#define NB     79            // ceil(10000/128)
#define NPAD   (NB * 128)    // 10112
#define LDOUT  10000
#define CAND_MAX 2048
#define DELTA  1e-2f

// ---------------- scratch (static device globals: allocation-free) ----------
__device__ float g_x1[NPAD * DIM];
__device__ float g_e [NPAD * DIM];
__device__ __nv_bfloat16 g_ehi[NPAD * DIM];

// ================= helpers =================
__device__ __forceinline__ uint32_t smem_u32(const void* p) {
    uint32_t a;
    asm("{ .reg .u64 t; cvta.to.shared.u64 t, %1; cvt.u32.u64 %0, t; }" : "=r"(a) : "l"(p));
    return a;
}
__device__ __forceinline__ void cp16(uint32_t dst, const void* src) {
    asm volatile("cp.async.cg.shared.global [%0], [%1], 16;" :: "r"(dst), "l"(src));
}
#define CP_COMMIT() asm volatile("cp.async.commit_group;")
#define CP_WAIT0()  asm volatile("cp.async.wait_group 0;")

__device__ __forceinline__ void ldm_x4(uint32_t& r0, uint32_t& r1, uint32_t& r2, uint32_t& r3,
                                       uint32_t addr) {
    asm volatile("ldmatrix.sync.aligned.m8n8.x4.shared.b16 {%0,%1,%2,%3}, [%4];"
                 : "=r"(r0), "=r"(r1), "=r"(r2), "=r"(r3) : "r"(addr));
}
__device__ __forceinline__ void ldm_x2(uint32_t& r0, uint32_t& r1, uint32_t addr) {
    asm volatile("ldmatrix.sync.aligned.m8n8.x2.shared.b16 {%0,%1}, [%2];"
                 : "=r"(r0), "=r"(r1) : "r"(addr));
}
__device__ __forceinline__ void mma_bf16(float* c, const uint32_t* a, const uint32_t* b) {
    asm volatile("mma.sync.aligned.m16n8k16.row.col.f32.bf16.bf16.f32 "
                 "{%0,%1,%2,%3}, {%4,%5,%6,%7}, {%8,%9}, {%0,%1,%2,%3};"
                 : "+f"(c[0]), "+f"(c[1]), "+f"(c[2]), "+f"(c[3])
                 : "r"(a[0]), "r"(a[1]), "r"(a[2]), "r"(a[3]), "r"(b[0]), "r"(b[1]));
}

// ---------------- shared GEMM core: C = act(A @ W^T + bias) -----------------
template<bool RELU, bool GUARD_A>
__device__ __forceinline__ void mlp_gemm_core(const float* __restrict__ A,
                                              const float* __restrict__ W,
                                              const float* __restrict__ bias,
                                              float* __restrict__ C, int mreal)
{
    __shared__ float As[16][128];
    __shared__ float Bs[16][128];
    const int tid  = threadIdx.x;
    const int tx   = tid & 15, ty = tid >> 4;
    const int row0 = ty * 8, col0 = tx * 8;
    const int br = blockIdx.x, bc = blockIdx.y;

    float c[8][8];
#pragma unroll
    for (int i = 0; i < 8; i++)
#pragma unroll
        for (int j = 0; j < 8; j++) c[i][j] = 0.f;

    for (int k0 = 0; k0 < DIM; k0 += 16) {
#pragma unroll
        for (int l = 0; l < 2; l++) {
            int idx = tid * 2 + l;
            int r   = idx >> 2;
            int c4  = (idx & 3) * 4;
            int arow = br * 128 + r;
            float4 v;
            if (!GUARD_A || arow < mreal)
                v = *reinterpret_cast<const float4*>(&A[(long)arow * DIM + k0 + c4]);
            else
                v = make_float4(0.f, 0.f, 0.f, 0.f);
            As[c4 + 0][r] = v.x; As[c4 + 1][r] = v.y;
            As[c4 + 2][r] = v.z; As[c4 + 3][r] = v.w;
            int wrow = bc * 128 + r;
            float4 w = *reinterpret_cast<const float4*>(&W[(long)wrow * DIM + k0 + c4]);
            Bs[c4 + 0][r] = w.x; Bs[c4 + 1][r] = w.y;
            Bs[c4 + 2][r] = w.z; Bs[c4 + 3][r] = w.w;
        }
        __syncthreads();
#pragma unroll
        for (int k = 0; k < 16; k++) {
            float a[8], b[8];
            *(float4*)&a[0] = *(const float4*)&As[k][row0];
            *(float4*)&a[4] = *(const float4*)&As[k][row0 + 4];
            *(float4*)&b[0] = *(const float4*)&Bs[k][col0];
            *(float4*)&b[4] = *(const float4*)&Bs[k][col0 + 4];
#pragma unroll
            for (int i = 0; i < 8; i++)
#pragma unroll
                for (int j = 0; j < 8; j++)
                    c[i][j] = fmaf(a[i], b[j], c[i][j]);
        }
        __syncthreads();
    }
#pragma unroll
    for (int i = 0; i < 8; i++) {
        int grow = br * 128 + row0 + i;
#pragma unroll
        for (int j = 0; j < 8; j++) {
            int gcol = bc * 128 + col0 + j;
            float v = c[i][j] + bias[gcol];
            if (RELU) v = fmaxf(v, 0.f);
            C[(long)grow * DIM + gcol] = v;
        }
    }
}

__global__ void mlp1_kernel(const float* __restrict__ h,
                            const float* __restrict__ W1,
                            const float* __restrict__ b1)
{
    mlp_gemm_core<true, true>(h, W1, b1, g_x1, N_ROWS);
}

__global__ void mlp2_kernel(const float* __restrict__ W2,
                            const float* __restrict__ b2)
{
    mlp_gemm_core<false, false>(g_x1, W2, b2, g_e, N_ROWS);
}

// -------- row L2-normalize; emit fp32 e and bf16; zero pads -----------------
__global__ void normalize_kernel()
{
    const int row = blockIdx.x;
    const int tid = threadIdx.x;           // 256 == DIM
    float v = g_e[(long)row * DIM + tid];
    float s = v * v;
#pragma unroll
    for (int off = 16; off > 0; off >>= 1)
        s += __shfl_xor_sync(0xffffffffu, s, off);
    __shared__ float warpsum[8];
    if ((tid & 31) == 0) warpsum[tid >> 5] = s;
    __syncthreads();
    float tot = 0.f;
#pragma unroll
    for (int w = 0; w < 8; w++) tot += warpsum[w];
    float denom = fmaxf(sqrtf(tot), 1e-12f);
    float e = (row < N_ROWS) ? v / denom : 0.f;
    g_e[(long)row * DIM + tid] = e;
    g_ehi[(long)row * DIM + tid] = __float2bfloat16(e);
}

// ---------------- approx adj via mma.sync bf16 (symmetric) ------------------
#define KT    32
#define APAD  40                         // row pitch in bf16 elems (80 B)
#define MATB  (128 * APAD * 2)           // 10240 B per matrix buffer
#define BUFB  (2 * MATB)                 // A+B per buffer
#define NCHUNK 8                         // 256 / 32

__global__ void __launch_bounds__(256, 2) adj_hmma_kernel(float* __restrict__ out)
{
    const int bc = blockIdx.x, br = blockIdx.y;
    if (bc < br) return;

    __shared__ __align__(16) char smem_raw[2 * BUFB];   // 40960 B
    const uint32_t sb = smem_u32(smem_raw);

    const int tid  = threadIdx.x;
    const int wid  = tid >> 5, lane = tid & 31;
    const int warp_m = wid >> 2, warp_n = wid & 3;      // 2 x 4 warp grid

    float acc[4][4][4];
#pragma unroll
    for (int mi = 0; mi < 4; mi++)
#pragma unroll
        for (int ni = 0; ni < 4; ni++)
#pragma unroll
            for (int q = 0; q < 4; q++) acc[mi][ni][q] = 0.f;

    const size_t aBase = (size_t)(br * 128) * DIM;
    const size_t bBase = (size_t)(bc * 128) * DIM;

    const int u0r = tid >> 2,         u0c = (tid & 3) * 16;
    const int u1r = (tid + 256) >> 2, u1c = u0c;

    auto issue = [&](int chunk, int buf) {
        const int kk = chunk * KT;
        const char* gA = (const char*)(g_ehi + aBase + kk);
        const char* gB = (const char*)(g_ehi + bBase + kk);
        uint32_t dA = sb + buf * BUFB;
        uint32_t dB = dA + MATB;
        cp16(dA + u0r * 80 + u0c, gA + (size_t)u0r * (DIM * 2) + u0c);
        cp16(dA + u1r * 80 + u1c, gA + (size_t)u1r * (DIM * 2) + u1c);
        cp16(dB + u0r * 80 + u0c, gB + (size_t)u0r * (DIM * 2) + u0c);
        cp16(dB + u1r * 80 + u1c, gB + (size_t)u1r * (DIM * 2) + u1c);
    };

    const uint32_t aAddr0 = sb + ((warp_m * 64 + (lane & 15)) * APAD) * 2 + (lane >> 4) * 16;
    const uint32_t bAddr0 = sb + MATB + ((warp_n * 32 + (lane & 7)) * APAD) * 2
                               + ((lane >> 3) & 1) * 16;

    issue(0, 0); CP_COMMIT(); CP_WAIT0(); __syncthreads();

#pragma unroll
    for (int c = 0; c < NCHUNK; ++c) {
        const int buf = c & 1;
        if (c + 1 < NCHUNK) { issue(c + 1, buf ^ 1); CP_COMMIT(); }

        const uint32_t aB = aAddr0 + buf * BUFB;
        const uint32_t bB = bAddr0 + buf * BUFB;
#pragma unroll
        for (int ks = 0; ks < 2; ++ks) {
            uint32_t afr[4][4], bfr[4][2];
#pragma unroll
            for (int mi = 0; mi < 4; mi++)
                ldm_x4(afr[mi][0], afr[mi][1], afr[mi][2], afr[mi][3],
                       aB + mi * (16 * APAD * 2) + ks * 32);
#pragma unroll
            for (int ni = 0; ni < 4; ni++)
                ldm_x2(bfr[ni][0], bfr[ni][1],
                       bB + ni * (8 * APAD * 2) + ks * 32);
#pragma unroll
            for (int mi = 0; mi < 4; mi++)
#pragma unroll
                for (int ni = 0; ni < 4; ni++)
                    mma_bf16(acc[mi][ni], afr[mi], bfr[ni]);
        }
        if (c + 1 < NCHUNK) { CP_WAIT0(); __syncthreads(); }
    }

    // ---- direct store of upper tile ----
#pragma unroll
    for (int mi = 0; mi < 4; mi++) {
        const int r0 = br * 128 + warp_m * 64 + mi * 16 + (lane >> 2);
#pragma unroll
        for (int ni = 0; ni < 4; ni++) {
            const int gc = bc * 128 + warp_n * 32 + ni * 8 + (lane & 3) * 2;
            if (gc < N_ROWS) {
                if (r0 < N_ROWS)
                    *reinterpret_cast<float2*>(&out[(long)r0 * LDOUT + gc]) =
                        make_float2(acc[mi][ni][0], acc[mi][ni][1]);
                if (r0 + 8 < N_ROWS)
                    *reinterpret_cast<float2*>(&out[(long)(r0 + 8) * LDOUT + gc]) =
                        make_float2(acc[mi][ni][2], acc[mi][ni][3]);
            }
        }
    }

    // ---- mirrored store via smem transpose (skip diagonal) ----
    if (br != bc) {
        float* Tf = reinterpret_cast<float*>(smem_raw);   // [128 cols][68 rows]
#pragma unroll
        for (int h = 0; h < 2; ++h) {
            __syncthreads();
            if (warp_m == h) {
#pragma unroll
                for (int mi = 0; mi < 4; mi++) {
                    const int rl = mi * 16 + (lane >> 2);
#pragma unroll
                    for (int ni = 0; ni < 4; ni++) {
                        const int cl = warp_n * 32 + ni * 8 + (lane & 3) * 2;
                        Tf[cl * 68 + rl]           = acc[mi][ni][0];
                        Tf[(cl + 1) * 68 + rl]     = acc[mi][ni][1];
                        Tf[cl * 68 + rl + 8]       = acc[mi][ni][2];
                        Tf[(cl + 1) * 68 + rl + 8] = acc[mi][ni][3];
                    }
                }
            }
            __syncthreads();
#pragma unroll
            for (int p = 0; p < 8; ++p) {
                const int idx = tid + p * 256;
                const int i = idx >> 4;
                const int j = idx & 15;
                const int grow2 = bc * 128 + i;
                if (grow2 < N_ROWS) {
                    long base = (long)grow2 * LDOUT + br * 128 + h * 64 + j * 4;
                    float4 v;
                    v.x = Tf[i * 68 + j * 4 + 0];
                    v.y = Tf[i * 68 + j * 4 + 1];
                    v.z = Tf[i * 68 + j * 4 + 2];
                    v.w = Tf[i * 68 + j * 4 + 3];
                    *reinterpret_cast<float4*>(&out[base]) = v;
                }
            }
        }
    }
}

// ---- fused select: register-resident row, 2-level radix, exact rescore -----
__device__ __forceinline__ unsigned fkey(float f)
{
    unsigned u = __float_as_uint(f);
    return (u & 0x80000000u) ? ~u : (u | 0x80000000u);
}
__device__ __forceinline__ float kinv(unsigned key)
{
    unsigned u = (key & 0x80000000u) ? (key & 0x7fffffffu) : ~key;
    return __uint_as_float(u);
}

__global__ void __launch_bounds__(256) select_kernel(float* __restrict__ out,
                                                     const int* __restrict__ kp)
{
    __shared__ unsigned hist[4096];
    __shared__ unsigned chunkSum[256];
    __shared__ float erow[DIM];
    __shared__ float cval[CAND_MAX];
    __shared__ int   cidx[CAND_MAX];
    __shared__ int candCnt;
    __shared__ unsigned sh_b1, sh_r1, sh_b2;

    const int row = blockIdx.x;
    const int tid = threadIdx.x;
    float* rowp = out + (long)row * LDOUT;
    const float4* r4 = reinterpret_cast<const float4*>(rowp);
    const unsigned K1 = (unsigned)(kp[0] + 1);

    // ---- single read of the row into registers (as monotonic keys) ----
    unsigned key[40];
#pragma unroll
    for (int i = 0; i < 10; ++i) {
        int idx4 = i * 256 + tid;              // float4 index, 2500 total
        if (idx4 < LDOUT / 4) {
            float4 v = r4[idx4];
            key[i * 4 + 0] = fkey(v.x);
            key[i * 4 + 1] = fkey(v.y);
            key[i * 4 + 2] = fkey(v.z);
            key[i * 4 + 3] = fkey(v.w);
        } else {
            key[i * 4 + 0] = 0u; key[i * 4 + 1] = 0u;
            key[i * 4 + 2] = 0u; key[i * 4 + 3] = 0u;   // minimal keys, never selected
        }
    }

    for (int i = tid; i < 4096; i += 256) hist[i] = 0;
    if (tid == 0) candCnt = 0;
    erow[tid] = g_e[(long)row * DIM + tid];
    __syncthreads();

    // ---- pass 1: top-12-bit histogram (from registers) ----
#pragma unroll
    for (int j = 0; j < 40; ++j) atomicAdd(&hist[key[j] >> 20], 1u);
    __syncthreads();
    {
        unsigned s = 0;
#pragma unroll
        for (int b = 0; b < 16; b++) s += hist[tid * 16 + b];
        chunkSum[tid] = s;
    }
    __syncthreads();
    if (tid == 0) {
        unsigned cum = 0;
        for (int t = 255; t >= 0; --t) {
            if (cum + chunkSum[t] >= K1) {
                for (int b = t * 16 + 15; b >= t * 16; --b) {
                    unsigned hh = hist[b];
                    if (cum + hh >= K1) { sh_b1 = (unsigned)b; sh_r1 = K1 - cum; break; }
                    cum += hh;
                }
                break;
            }
            cum += chunkSum[t];
        }
    }
    __syncthreads();
    const unsigned b1 = sh_b1, r1 = sh_r1;

    // ---- pass 2: refine next 12 bits inside bin b1 (from registers) ----
    for (int i = tid; i < 4096; i += 256) hist[i] = 0;
    __syncthreads();
#pragma unroll
    for (int j = 0; j < 40; ++j) {
        unsigned u = key[j];
        if ((u >> 20) == b1) atomicAdd(&hist[(u >> 8) & 0xFFFu], 1u);
    }
    __syncthreads();
    {
        unsigned s = 0;
#pragma unroll
        for (int b = 0; b < 16; b++) s += hist[tid * 16 + b];
        chunkSum[tid] = s;
    }
    __syncthreads();
    if (tid == 0) {
        unsigned cum = 0;
        sh_b2 = 0;
        for (int t = 255; t >= 0; --t) {
            if (cum + chunkSum[t] >= r1) {
                for (int b = t * 16 + 15; b >= t * 16; --b) {
                    unsigned hh = hist[b];
                    if (cum + hh >= r1) { sh_b2 = (unsigned)b; break; }
                    cum += hh;
                }
                break;
            }
            cum += chunkSum[t];
        }
    }
    __syncthreads();

    // threshold with margin (covers bf16 GEMM error, worst-case 2^-8)
    const unsigned F = (b1 << 20) | (sh_b2 << 8);
    const unsigned Tm = fkey(kinv(F) - DELTA);

    // ---- collect candidates from registers; stream zeros to the row ----
    const float4 z = make_float4(0.f, 0.f, 0.f, 0.f);
#pragma unroll
    for (int i = 0; i < 10; ++i) {
        int idx4 = i * 256 + tid;
#pragma unroll
        for (int q = 0; q < 4; ++q) {
            if (key[i * 4 + q] >= Tm) {
                int p = atomicAdd(&candCnt, 1);
                if (p < CAND_MAX) cidx[p] = idx4 * 4 + q;
            }
        }
        if (idx4 < LDOUT / 4)
            reinterpret_cast<float4*>(rowp)[idx4] = z;
    }
    __syncthreads();
    const int n = candCnt < CAND_MAX ? candCnt : CAND_MAX;

    // ---- exact fp32 rescore ----
    for (int c = tid; c < n; c += 256) {
        const float* ec = &g_e[(long)cidx[c] * DIM];
        float a = 0.f;
#pragma unroll 8
        for (int k = 0; k < DIM; ++k) a = fmaf(erow[k], ec[k], a);
        cval[c] = a;
    }
    __syncthreads();

    // ---- rank (val desc, idx asc) and scatter kept entries ----
    for (int c = tid; c < n; c += 256) {
        float v = cval[c];
        int  id = cidx[c];
        int rank = 0;
        for (int o = 0; o < n; ++o) {
            float vo = cval[o];
            rank += (vo > v) || (vo == v && cidx[o] < id);
        }
        if (rank < (int)K1) rowp[id] = fmaxf(v, 0.f);
    }
}

// ---------------- launch ----------------------------------------------------
extern "C" void kernel_launch(void* const* d_in, const int* in_sizes, int n_in,
                              void* d_out, int out_size)
{
    const float* h  = (const float*)d_in[0];
    const float* W1 = (const float*)d_in[1];
    const float* b1 = (const float*)d_in[2];
    const float* W2 = (const float*)d_in[3];
    const float* b2 = (const float*)d_in[4];
    const int*   kp = (const int*)  d_in[5];
    float* out = (float*)d_out;

    mlp1_kernel<<<dim3(NB, 2), 256>>>(h, W1, b1);
    mlp2_kernel<<<dim3(NB, 2), 256>>>(W2, b2);
    normalize_kernel<<<NPAD, 256>>>();
    adj_hmma_kernel<<<dim3(NB, NB), 256>>>(out);
    select_kernel<<<N_ROWS, 256>>>(out, kp);
}

// round 13
// speedup vs baseline: 1.7536x; 1.2910x over previous
#include <cuda_runtime.h>
#include <cuda_bf16.h>
#include <cstdint>

#define N_ROWS 10000
#define DIM    256
#define NB     79            // ceil(10000/128)
#define NPAD   (NB * 128)    // 10112
#define LDOUT  10000
#define CAND_MAX 2048
#define CAP     3072
#define DELTA  1e-2f

// ---------------- scratch (static device globals: allocation-free) ----------
__device__ float g_x1[NPAD * DIM];
__device__ float g_e [NPAD * DIM];
__device__ __nv_bfloat16 g_ehi[NPAD * DIM];

// ================= helpers =================
__device__ __forceinline__ uint32_t smem_u32(const void* p) {
    uint32_t a;
    asm("{ .reg .u64 t; cvta.to.shared.u64 t, %1; cvt.u32.u64 %0, t; }" : "=r"(a) : "l"(p));
    return a;
}
__device__ __forceinline__ void cp16(uint32_t dst, const void* src) {
    asm volatile("cp.async.cg.shared.global [%0], [%1], 16;" :: "r"(dst), "l"(src));
}
#define CP_COMMIT() asm volatile("cp.async.commit_group;")
#define CP_WAIT0()  asm volatile("cp.async.wait_group 0;")

__device__ __forceinline__ void ldm_x4(uint32_t& r0, uint32_t& r1, uint32_t& r2, uint32_t& r3,
                                       uint32_t addr) {
    asm volatile("ldmatrix.sync.aligned.m8n8.x4.shared.b16 {%0,%1,%2,%3}, [%4];"
                 : "=r"(r0), "=r"(r1), "=r"(r2), "=r"(r3) : "r"(addr));
}
__device__ __forceinline__ void ldm_x2(uint32_t& r0, uint32_t& r1, uint32_t addr) {
    asm volatile("ldmatrix.sync.aligned.m8n8.x2.shared.b16 {%0,%1}, [%2];"
                 : "=r"(r0), "=r"(r1) : "r"(addr));
}
__device__ __forceinline__ void mma_bf16(float* c, const uint32_t* a, const uint32_t* b) {
    asm volatile("mma.sync.aligned.m16n8k16.row.col.f32.bf16.bf16.f32 "
                 "{%0,%1,%2,%3}, {%4,%5,%6,%7}, {%8,%9}, {%0,%1,%2,%3};"
                 : "+f"(c[0]), "+f"(c[1]), "+f"(c[2]), "+f"(c[3])
                 : "r"(a[0]), "r"(a[1]), "r"(a[2]), "r"(a[3]), "r"(b[0]), "r"(b[1]));
}

// ---------------- shared GEMM core: C = act(A @ W^T + bias) -----------------
template<bool RELU, bool GUARD_A>
__device__ __forceinline__ void mlp_gemm_core(const float* __restrict__ A,
                                              const float* __restrict__ W,
                                              const float* __restrict__ bias,
                                              float* __restrict__ C, int mreal)
{
    __shared__ float As[16][128];
    __shared__ float Bs[16][128];
    const int tid  = threadIdx.x;
    const int tx   = tid & 15, ty = tid >> 4;
    const int row0 = ty * 8, col0 = tx * 8;
    const int br = blockIdx.x, bc = blockIdx.y;

    float c[8][8];
#pragma unroll
    for (int i = 0; i < 8; i++)
#pragma unroll
        for (int j = 0; j < 8; j++) c[i][j] = 0.f;

    for (int k0 = 0; k0 < DIM; k0 += 16) {
#pragma unroll
        for (int l = 0; l < 2; l++) {
            int idx = tid * 2 + l;
            int r   = idx >> 2;
            int c4  = (idx & 3) * 4;
            int arow = br * 128 + r;
            float4 v;
            if (!GUARD_A || arow < mreal)
                v = *reinterpret_cast<const float4*>(&A[(long)arow * DIM + k0 + c4]);
            else
                v = make_float4(0.f, 0.f, 0.f, 0.f);
            As[c4 + 0][r] = v.x; As[c4 + 1][r] = v.y;
            As[c4 + 2][r] = v.z; As[c4 + 3][r] = v.w;
            int wrow = bc * 128 + r;
            float4 w = *reinterpret_cast<const float4*>(&W[(long)wrow * DIM + k0 + c4]);
            Bs[c4 + 0][r] = w.x; Bs[c4 + 1][r] = w.y;
            Bs[c4 + 2][r] = w.z; Bs[c4 + 3][r] = w.w;
        }
        __syncthreads();
#pragma unroll
        for (int k = 0; k < 16; k++) {
            float a[8], b[8];
            *(float4*)&a[0] = *(const float4*)&As[k][row0];
            *(float4*)&a[4] = *(const float4*)&As[k][row0 + 4];
            *(float4*)&b[0] = *(const float4*)&Bs[k][col0];
            *(float4*)&b[4] = *(const float4*)&Bs[k][col0 + 4];
#pragma unroll
            for (int i = 0; i < 8; i++)
#pragma unroll
                for (int j = 0; j < 8; j++)
                    c[i][j] = fmaf(a[i], b[j], c[i][j]);
        }
        __syncthreads();
    }
#pragma unroll
    for (int i = 0; i < 8; i++) {
        int grow = br * 128 + row0 + i;
#pragma unroll
        for (int j = 0; j < 8; j++) {
            int gcol = bc * 128 + col0 + j;
            float v = c[i][j] + bias[gcol];
            if (RELU) v = fmaxf(v, 0.f);
            C[(long)grow * DIM + gcol] = v;
        }
    }
}

__global__ void mlp1_kernel(const float* __restrict__ h,
                            const float* __restrict__ W1,
                            const float* __restrict__ b1)
{
    mlp_gemm_core<true, true>(h, W1, b1, g_x1, N_ROWS);
}

__global__ void mlp2_kernel(const float* __restrict__ W2,
                            const float* __restrict__ b2)
{
    mlp_gemm_core<false, false>(g_x1, W2, b2, g_e, N_ROWS);
}

// -------- row L2-normalize; emit fp32 e and bf16; zero pads -----------------
__global__ void normalize_kernel()
{
    const int row = blockIdx.x;
    const int tid = threadIdx.x;           // 256 == DIM
    float v = g_e[(long)row * DIM + tid];
    float s = v * v;
#pragma unroll
    for (int off = 16; off > 0; off >>= 1)
        s += __shfl_xor_sync(0xffffffffu, s, off);
    __shared__ float warpsum[8];
    if ((tid & 31) == 0) warpsum[tid >> 5] = s;
    __syncthreads();
    float tot = 0.f;
#pragma unroll
    for (int w = 0; w < 8; w++) tot += warpsum[w];
    float denom = fmaxf(sqrtf(tot), 1e-12f);
    float e = (row < N_ROWS) ? v / denom : 0.f;
    g_e[(long)row * DIM + tid] = e;
    g_ehi[(long)row * DIM + tid] = __float2bfloat16(e);
}

// ---------------- approx adj via mma.sync bf16 (symmetric) ------------------
#define KT    32
#define APAD  40                         // row pitch in bf16 elems (80 B)
#define MATB  (128 * APAD * 2)           // 10240 B per matrix buffer
#define BUFB  (2 * MATB)                 // A+B per buffer
#define NCHUNK 8                         // 256 / 32

__global__ void __launch_bounds__(256, 2) adj_hmma_kernel(float* __restrict__ out)
{
    const int bc = blockIdx.x, br = blockIdx.y;
    if (bc < br) return;

    __shared__ __align__(16) char smem_raw[2 * BUFB];   // 40960 B
    const uint32_t sb = smem_u32(smem_raw);

    const int tid  = threadIdx.x;
    const int wid  = tid >> 5, lane = tid & 31;
    const int warp_m = wid >> 2, warp_n = wid & 3;      // 2 x 4 warp grid

    float acc[4][4][4];
#pragma unroll
    for (int mi = 0; mi < 4; mi++)
#pragma unroll
        for (int ni = 0; ni < 4; ni++)
#pragma unroll
            for (int q = 0; q < 4; q++) acc[mi][ni][q] = 0.f;

    const size_t aBase = (size_t)(br * 128) * DIM;
    const size_t bBase = (size_t)(bc * 128) * DIM;

    const int u0r = tid >> 2,         u0c = (tid & 3) * 16;
    const int u1r = (tid + 256) >> 2, u1c = u0c;

    auto issue = [&](int chunk, int buf) {
        const int kk = chunk * KT;
        const char* gA = (const char*)(g_ehi + aBase + kk);
        const char* gB = (const char*)(g_ehi + bBase + kk);
        uint32_t dA = sb + buf * BUFB;
        uint32_t dB = dA + MATB;
        cp16(dA + u0r * 80 + u0c, gA + (size_t)u0r * (DIM * 2) + u0c);
        cp16(dA + u1r * 80 + u1c, gA + (size_t)u1r * (DIM * 2) + u1c);
        cp16(dB + u0r * 80 + u0c, gB + (size_t)u0r * (DIM * 2) + u0c);
        cp16(dB + u1r * 80 + u1c, gB + (size_t)u1r * (DIM * 2) + u1c);
    };

    const uint32_t aAddr0 = sb + ((warp_m * 64 + (lane & 15)) * APAD) * 2 + (lane >> 4) * 16;
    const uint32_t bAddr0 = sb + MATB + ((warp_n * 32 + (lane & 7)) * APAD) * 2
                               + ((lane >> 3) & 1) * 16;

    issue(0, 0); CP_COMMIT(); CP_WAIT0(); __syncthreads();

#pragma unroll
    for (int c = 0; c < NCHUNK; ++c) {
        const int buf = c & 1;
        if (c + 1 < NCHUNK) { issue(c + 1, buf ^ 1); CP_COMMIT(); }

        const uint32_t aB = aAddr0 + buf * BUFB;
        const uint32_t bB = bAddr0 + buf * BUFB;
#pragma unroll
        for (int ks = 0; ks < 2; ++ks) {
            uint32_t afr[4][4], bfr[4][2];
#pragma unroll
            for (int mi = 0; mi < 4; mi++)
                ldm_x4(afr[mi][0], afr[mi][1], afr[mi][2], afr[mi][3],
                       aB + mi * (16 * APAD * 2) + ks * 32);
#pragma unroll
            for (int ni = 0; ni < 4; ni++)
                ldm_x2(bfr[ni][0], bfr[ni][1],
                       bB + ni * (8 * APAD * 2) + ks * 32);
#pragma unroll
            for (int mi = 0; mi < 4; mi++)
#pragma unroll
                for (int ni = 0; ni < 4; ni++)
                    mma_bf16(acc[mi][ni], afr[mi], bfr[ni]);
        }
        if (c + 1 < NCHUNK) { CP_WAIT0(); __syncthreads(); }
    }

    // ---- direct store of upper tile ----
#pragma unroll
    for (int mi = 0; mi < 4; mi++) {
        const int r0 = br * 128 + warp_m * 64 + mi * 16 + (lane >> 2);
#pragma unroll
        for (int ni = 0; ni < 4; ni++) {
            const int gc = bc * 128 + warp_n * 32 + ni * 8 + (lane & 3) * 2;
            if (gc < N_ROWS) {
                if (r0 < N_ROWS)
                    *reinterpret_cast<float2*>(&out[(long)r0 * LDOUT + gc]) =
                        make_float2(acc[mi][ni][0], acc[mi][ni][1]);
                if (r0 + 8 < N_ROWS)
                    *reinterpret_cast<float2*>(&out[(long)(r0 + 8) * LDOUT + gc]) =
                        make_float2(acc[mi][ni][2], acc[mi][ni][3]);
            }
        }
    }

    // ---- mirrored store via smem transpose (skip diagonal) ----
    if (br != bc) {
        float* Tf = reinterpret_cast<float*>(smem_raw);   // [128 cols][68 rows]
#pragma unroll
        for (int h = 0; h < 2; ++h) {
            __syncthreads();
            if (warp_m == h) {
#pragma unroll
                for (int mi = 0; mi < 4; mi++) {
                    const int rl = mi * 16 + (lane >> 2);
#pragma unroll
                    for (int ni = 0; ni < 4; ni++) {
                        const int cl = warp_n * 32 + ni * 8 + (lane & 3) * 2;
                        Tf[cl * 68 + rl]           = acc[mi][ni][0];
                        Tf[(cl + 1) * 68 + rl]     = acc[mi][ni][1];
                        Tf[cl * 68 + rl + 8]       = acc[mi][ni][2];
                        Tf[(cl + 1) * 68 + rl + 8] = acc[mi][ni][3];
                    }
                }
            }
            __syncthreads();
#pragma unroll
            for (int p = 0; p < 8; ++p) {
                const int idx = tid + p * 256;
                const int i = idx >> 4;
                const int j = idx & 15;
                const int grow2 = bc * 128 + i;
                if (grow2 < N_ROWS) {
                    long base = (long)grow2 * LDOUT + br * 128 + h * 64 + j * 4;
                    float4 v;
                    v.x = Tf[i * 68 + j * 4 + 0];
                    v.y = Tf[i * 68 + j * 4 + 1];
                    v.z = Tf[i * 68 + j * 4 + 2];
                    v.w = Tf[i * 68 + j * 4 + 3];
                    *reinterpret_cast<float4*>(&out[base]) = v;
                }
            }
        }
    }
}

// ---- fused select: 2 sweeps (hist; refine+collect+zero), exact rescore -----
// Shared-memory aliasing (lifetimes disjoint, separated by __syncthreads):
//   hist[4096]  --(after b2 picked)--> cidx[<=4096]
//   skey[CAP]   --(after prune)-----> cval[<=CAP]
__device__ __forceinline__ unsigned fkey(float f)
{
    unsigned u = __float_as_uint(f);
    return (u & 0x80000000u) ? ~u : (u | 0x80000000u);
}
__device__ __forceinline__ float kinv(unsigned key)
{
    unsigned u = (key & 0x80000000u) ? (key & 0x7fffffffu) : ~key;
    return __uint_as_float(u);
}

__global__ void __launch_bounds__(256) select_kernel(float* __restrict__ out,
                                                     const int* __restrict__ kp)
{
    __shared__ unsigned hist[4096];        // -> cidx after refine pick
    __shared__ unsigned chunkSum[256];
    __shared__ float erow[DIM];
    __shared__ unsigned skey[CAP];         // -> cval after prune
    __shared__ int      sidx[CAP];
    __shared__ int stageCnt, candCnt;
    __shared__ unsigned sh_b1, sh_r1, sh_b2;

    int*   cidx = reinterpret_cast<int*>(hist);
    float* cval = reinterpret_cast<float*>(skey);

    const int row = blockIdx.x;
    const int tid = threadIdx.x;
    float* rowp = out + (long)row * LDOUT;
    const float4* r4 = reinterpret_cast<const float4*>(rowp);
    const unsigned K1 = (unsigned)(kp[0] + 1);

    for (int i = tid; i < 4096; i += 256) hist[i] = 0;
    if (tid == 0) { stageCnt = 0; candCnt = 0; }
    erow[tid] = g_e[(long)row * DIM + tid];
    __syncthreads();

    // ---- sweep 1: top-12-bit histogram (DRAM read) ----
    for (int i = tid; i < LDOUT / 4; i += 256) {
        float4 v = r4[i];
        atomicAdd(&hist[fkey(v.x) >> 20], 1u);
        atomicAdd(&hist[fkey(v.y) >> 20], 1u);
        atomicAdd(&hist[fkey(v.z) >> 20], 1u);
        atomicAdd(&hist[fkey(v.w) >> 20], 1u);
    }
    __syncthreads();
    {
        unsigned s = 0;
#pragma unroll
        for (int b = 0; b < 16; b++) s += hist[tid * 16 + b];
        chunkSum[tid] = s;
    }
    __syncthreads();
    if (tid == 0) {
        unsigned cum = 0;
        for (int t = 255; t >= 0; --t) {
            if (cum + chunkSum[t] >= K1) {
                for (int b = t * 16 + 15; b >= t * 16; --b) {
                    unsigned hh = hist[b];
                    if (cum + hh >= K1) { sh_b1 = (unsigned)b; sh_r1 = K1 - cum; break; }
                    cum += hh;
                }
                break;
            }
            cum += chunkSum[t];
        }
    }
    __syncthreads();
    const unsigned b1 = sh_b1, r1 = sh_r1;

    // zero refine histogram before sweep 2
    for (int i = tid; i < 4096; i += 256) hist[i] = 0;
    __syncthreads();

    // pre-threshold: anything that can survive final Tm has key >= Kpre
    // (Tm = refined_floor - DELTA >= binfloor(b1) - DELTA = kinv(Kpre))
    const unsigned Kpre = fkey(kinv(b1 << 20) - DELTA);

    // ---- sweep 2: refine hist + stage candidates + zero the row (L2) ----
    const float4 z = make_float4(0.f, 0.f, 0.f, 0.f);
    for (int i = tid; i < LDOUT / 4; i += 256) {
        float4 v = r4[i];
        const float* pv = &v.x;
#pragma unroll
        for (int q = 0; q < 4; ++q) {
            unsigned u = fkey(pv[q]);
            if (u >= Kpre) {
                int p = atomicAdd(&stageCnt, 1);
                if (p < CAP) { skey[p] = u; sidx[p] = i * 4 + q; }
            }
            if ((u >> 20) == b1) atomicAdd(&hist[(u >> 8) & 0xFFFu], 1u);
        }
        reinterpret_cast<float4*>(rowp)[i] = z;
    }
    __syncthreads();
    {
        unsigned s = 0;
#pragma unroll
        for (int b = 0; b < 16; b++) s += hist[tid * 16 + b];
        chunkSum[tid] = s;
    }
    __syncthreads();
    if (tid == 0) {
        unsigned cum = 0;
        sh_b2 = 0;
        for (int t = 255; t >= 0; --t) {
            if (cum + chunkSum[t] >= r1) {
                for (int b = t * 16 + 15; b >= t * 16; --b) {
                    unsigned hh = hist[b];
                    if (cum + hh >= r1) { sh_b2 = (unsigned)b; break; }
                    cum += hh;
                }
                break;
            }
            cum += chunkSum[t];
        }
    }
    __syncthreads();

    // final threshold with margin (same as measured-best round 9)
    const unsigned F = (b1 << 20) | (sh_b2 << 8);
    const unsigned Tm = fkey(kinv(F) - DELTA);

    // ---- prune staged -> final candidate list (cidx aliases hist) ----
    const int ns = stageCnt < CAP ? stageCnt : CAP;
    for (int c = tid; c < ns; c += 256) {
        if (skey[c] >= Tm) {
            int p = atomicAdd(&candCnt, 1);
            if (p < CAND_MAX) cidx[p] = sidx[c];
        }
    }
    __syncthreads();
    const int n = candCnt < CAND_MAX ? candCnt : CAND_MAX;

    // ---- exact fp32 rescore (cval aliases skey; prune is done) ----
    for (int c = tid; c < n; c += 256) {
        const float* ec = &g_e[(long)cidx[c] * DIM];
        float a = 0.f;
#pragma unroll 8
        for (int k = 0; k < DIM; ++k) a = fmaf(erow[k], ec[k], a);
        cval[c] = a;
    }
    __syncthreads();

    // ---- rank (val desc, idx asc) and scatter kept entries ----
    for (int c = tid; c < n; c += 256) {
        float v = cval[c];
        int  id = cidx[c];
        int rank = 0;
        for (int o = 0; o < n; ++o) {
            float vo = cval[o];
            rank += (vo > v) || (vo == v && cidx[o] < id);
        }
        if (rank < (int)K1) rowp[id] = fmaxf(v, 0.f);
    }
}

// ---------------- launch ----------------------------------------------------
extern "C" void kernel_launch(void* const* d_in, const int* in_sizes, int n_in,
                              void* d_out, int out_size)
{
    const float* h  = (const float*)d_in[0];
    const float* W1 = (const float*)d_in[1];
    const float* b1 = (const float*)d_in[2];
    const float* W2 = (const float*)d_in[3];
    const float* b2 = (const float*)d_in[4];
    const int*   kp = (const int*)  d_in[5];
    float* out = (float*)d_out;

    mlp1_kernel<<<dim3(NB, 2), 256>>>(h, W1, b1);
    mlp2_kernel<<<dim3(NB, 2), 256>>>(W2, b2);
    normalize_kernel<<<NPAD, 256>>>();
    adj_hmma_kernel<<<dim3(NB, NB), 256>>>(out);
    select_kernel<<<N_ROWS, 256>>>(out, kp);
}

// round 15
// speedup vs baseline: 1.8239x; 1.0401x over previous
#include <cuda_runtime.h>
#include <cuda_bf16.h>
#include <cstdint>

#define N_ROWS 10000
#define DIM    256
#define NB     79            // ceil(10000/128)
#define NPAD   (NB * 128)    // 10112
#define LDOUT  10000
#define CAND_MAX 2048
#define CAP     3072
#define DELTA  1e-2f
#define STH    512           // select threads per block

// ---------------- scratch (static device globals: allocation-free) ----------
__device__ float g_x1[NPAD * DIM];
__device__ float g_e [NPAD * DIM];
__device__ __nv_bfloat16 g_ehi[NPAD * DIM];

// ================= helpers =================
__device__ __forceinline__ uint32_t smem_u32(const void* p) {
    uint32_t a;
    asm("{ .reg .u64 t; cvta.to.shared.u64 t, %1; cvt.u32.u64 %0, t; }" : "=r"(a) : "l"(p));
    return a;
}
__device__ __forceinline__ void cp16(uint32_t dst, const void* src) {
    asm volatile("cp.async.cg.shared.global [%0], [%1], 16;" :: "r"(dst), "l"(src));
}
#define CP_COMMIT() asm volatile("cp.async.commit_group;")
#define CP_WAIT0()  asm volatile("cp.async.wait_group 0;")

__device__ __forceinline__ void ldm_x4(uint32_t& r0, uint32_t& r1, uint32_t& r2, uint32_t& r3,
                                       uint32_t addr) {
    asm volatile("ldmatrix.sync.aligned.m8n8.x4.shared.b16 {%0,%1,%2,%3}, [%4];"
                 : "=r"(r0), "=r"(r1), "=r"(r2), "=r"(r3) : "r"(addr));
}
__device__ __forceinline__ void ldm_x2(uint32_t& r0, uint32_t& r1, uint32_t addr) {
    asm volatile("ldmatrix.sync.aligned.m8n8.x2.shared.b16 {%0,%1}, [%2];"
                 : "=r"(r0), "=r"(r1) : "r"(addr));
}
__device__ __forceinline__ void mma_bf16(float* c, const uint32_t* a, const uint32_t* b) {
    asm volatile("mma.sync.aligned.m16n8k16.row.col.f32.bf16.bf16.f32 "
                 "{%0,%1,%2,%3}, {%4,%5,%6,%7}, {%8,%9}, {%0,%1,%2,%3};"
                 : "+f"(c[0]), "+f"(c[1]), "+f"(c[2]), "+f"(c[3])
                 : "r"(a[0]), "r"(a[1]), "r"(a[2]), "r"(a[3]), "r"(b[0]), "r"(b[1]));
}

// ---------------- shared GEMM core: C = act(A @ W^T + bias) -----------------
template<bool RELU, bool GUARD_A>
__device__ __forceinline__ void mlp_gemm_core(const float* __restrict__ A,
                                              const float* __restrict__ W,
                                              const float* __restrict__ bias,
                                              float* __restrict__ C, int mreal)
{
    __shared__ float As[16][128];
    __shared__ float Bs[16][128];
    const int tid  = threadIdx.x;
    const int tx   = tid & 15, ty = tid >> 4;
    const int row0 = ty * 8, col0 = tx * 8;
    const int br = blockIdx.x, bc = blockIdx.y;

    float c[8][8];
#pragma unroll
    for (int i = 0; i < 8; i++)
#pragma unroll
        for (int j = 0; j < 8; j++) c[i][j] = 0.f;

    for (int k0 = 0; k0 < DIM; k0 += 16) {
#pragma unroll
        for (int l = 0; l < 2; l++) {
            int idx = tid * 2 + l;
            int r   = idx >> 2;
            int c4  = (idx & 3) * 4;
            int arow = br * 128 + r;
            float4 v;
            if (!GUARD_A || arow < mreal)
                v = *reinterpret_cast<const float4*>(&A[(long)arow * DIM + k0 + c4]);
            else
                v = make_float4(0.f, 0.f, 0.f, 0.f);
            As[c4 + 0][r] = v.x; As[c4 + 1][r] = v.y;
            As[c4 + 2][r] = v.z; As[c4 + 3][r] = v.w;
            int wrow = bc * 128 + r;
            float4 w = *reinterpret_cast<const float4*>(&W[(long)wrow * DIM + k0 + c4]);
            Bs[c4 + 0][r] = w.x; Bs[c4 + 1][r] = w.y;
            Bs[c4 + 2][r] = w.z; Bs[c4 + 3][r] = w.w;
        }
        __syncthreads();
#pragma unroll
        for (int k = 0; k < 16; k++) {
            float a[8], b[8];
            *(float4*)&a[0] = *(const float4*)&As[k][row0];
            *(float4*)&a[4] = *(const float4*)&As[k][row0 + 4];
            *(float4*)&b[0] = *(const float4*)&Bs[k][col0];
            *(float4*)&b[4] = *(const float4*)&Bs[k][col0 + 4];
#pragma unroll
            for (int i = 0; i < 8; i++)
#pragma unroll
                for (int j = 0; j < 8; j++)
                    c[i][j] = fmaf(a[i], b[j], c[i][j]);
        }
        __syncthreads();
    }
#pragma unroll
    for (int i = 0; i < 8; i++) {
        int grow = br * 128 + row0 + i;
#pragma unroll
        for (int j = 0; j < 8; j++) {
            int gcol = bc * 128 + col0 + j;
            float v = c[i][j] + bias[gcol];
            if (RELU) v = fmaxf(v, 0.f);
            C[(long)grow * DIM + gcol] = v;
        }
    }
}

__global__ void mlp1_kernel(const float* __restrict__ h,
                            const float* __restrict__ W1,
                            const float* __restrict__ b1)
{
    mlp_gemm_core<true, true>(h, W1, b1, g_x1, N_ROWS);
}

__global__ void mlp2_kernel(const float* __restrict__ W2,
                            const float* __restrict__ b2)
{
    mlp_gemm_core<false, false>(g_x1, W2, b2, g_e, N_ROWS);
}

// -------- row L2-normalize; emit fp32 e and bf16; zero pads -----------------
__global__ void normalize_kernel()
{
    const int row = blockIdx.x;
    const int tid = threadIdx.x;           // 256 == DIM
    float v = g_e[(long)row * DIM + tid];
    float s = v * v;
#pragma unroll
    for (int off = 16; off > 0; off >>= 1)
        s += __shfl_xor_sync(0xffffffffu, s, off);
    __shared__ float warpsum[8];
    if ((tid & 31) == 0) warpsum[tid >> 5] = s;
    __syncthreads();
    float tot = 0.f;
#pragma unroll
    for (int w = 0; w < 8; w++) tot += warpsum[w];
    float denom = fmaxf(sqrtf(tot), 1e-12f);
    float e = (row < N_ROWS) ? v / denom : 0.f;
    g_e[(long)row * DIM + tid] = e;
    g_ehi[(long)row * DIM + tid] = __float2bfloat16(e);
}

// ---------------- approx adj via mma.sync bf16 (symmetric) ------------------
#define KT    32
#define APAD  40                         // row pitch in bf16 elems (80 B)
#define MATB  (128 * APAD * 2)           // 10240 B per matrix buffer
#define BUFB  (2 * MATB)                 // A+B per buffer
#define NCHUNK 8                         // 256 / 32

__global__ void __launch_bounds__(256, 2) adj_hmma_kernel(float* __restrict__ out)
{
    const int bc = blockIdx.x, br = blockIdx.y;
    if (bc < br) return;

    __shared__ __align__(16) char smem_raw[2 * BUFB];   // 40960 B
    const uint32_t sb = smem_u32(smem_raw);

    const int tid  = threadIdx.x;
    const int wid  = tid >> 5, lane = tid & 31;
    const int warp_m = wid >> 2, warp_n = wid & 3;      // 2 x 4 warp grid

    float acc[4][4][4];
#pragma unroll
    for (int mi = 0; mi < 4; mi++)
#pragma unroll
        for (int ni = 0; ni < 4; ni++)
#pragma unroll
            for (int q = 0; q < 4; q++) acc[mi][ni][q] = 0.f;

    const size_t aBase = (size_t)(br * 128) * DIM;
    const size_t bBase = (size_t)(bc * 128) * DIM;

    const int u0r = tid >> 2,         u0c = (tid & 3) * 16;
    const int u1r = (tid + 256) >> 2, u1c = u0c;

    auto issue = [&](int chunk, int buf) {
        const int kk = chunk * KT;
        const char* gA = (const char*)(g_ehi + aBase + kk);
        const char* gB = (const char*)(g_ehi + bBase + kk);
        uint32_t dA = sb + buf * BUFB;
        uint32_t dB = dA + MATB;
        cp16(dA + u0r * 80 + u0c, gA + (size_t)u0r * (DIM * 2) + u0c);
        cp16(dA + u1r * 80 + u1c, gA + (size_t)u1r * (DIM * 2) + u1c);
        cp16(dB + u0r * 80 + u0c, gB + (size_t)u0r * (DIM * 2) + u0c);
        cp16(dB + u1r * 80 + u1c, gB + (size_t)u1r * (DIM * 2) + u1c);
    };

    const uint32_t aAddr0 = sb + ((warp_m * 64 + (lane & 15)) * APAD) * 2 + (lane >> 4) * 16;
    const uint32_t bAddr0 = sb + MATB + ((warp_n * 32 + (lane & 7)) * APAD) * 2
                               + ((lane >> 3) & 1) * 16;

    issue(0, 0); CP_COMMIT(); CP_WAIT0(); __syncthreads();

#pragma unroll
    for (int c = 0; c < NCHUNK; ++c) {
        const int buf = c & 1;
        if (c + 1 < NCHUNK) { issue(c + 1, buf ^ 1); CP_COMMIT(); }

        const uint32_t aB = aAddr0 + buf * BUFB;
        const uint32_t bB = bAddr0 + buf * BUFB;
#pragma unroll
        for (int ks = 0; ks < 2; ++ks) {
            uint32_t afr[4][4], bfr[4][2];
#pragma unroll
            for (int mi = 0; mi < 4; mi++)
                ldm_x4(afr[mi][0], afr[mi][1], afr[mi][2], afr[mi][3],
                       aB + mi * (16 * APAD * 2) + ks * 32);
#pragma unroll
            for (int ni = 0; ni < 4; ni++)
                ldm_x2(bfr[ni][0], bfr[ni][1],
                       bB + ni * (8 * APAD * 2) + ks * 32);
#pragma unroll
            for (int mi = 0; mi < 4; mi++)
#pragma unroll
                for (int ni = 0; ni < 4; ni++)
                    mma_bf16(acc[mi][ni], afr[mi], bfr[ni]);
        }
        if (c + 1 < NCHUNK) { CP_WAIT0(); __syncthreads(); }
    }

    // ---- direct store of upper tile ----
#pragma unroll
    for (int mi = 0; mi < 4; mi++) {
        const int r0 = br * 128 + warp_m * 64 + mi * 16 + (lane >> 2);
#pragma unroll
        for (int ni = 0; ni < 4; ni++) {
            const int gc = bc * 128 + warp_n * 32 + ni * 8 + (lane & 3) * 2;
            if (gc < N_ROWS) {
                if (r0 < N_ROWS)
                    *reinterpret_cast<float2*>(&out[(long)r0 * LDOUT + gc]) =
                        make_float2(acc[mi][ni][0], acc[mi][ni][1]);
                if (r0 + 8 < N_ROWS)
                    *reinterpret_cast<float2*>(&out[(long)(r0 + 8) * LDOUT + gc]) =
                        make_float2(acc[mi][ni][2], acc[mi][ni][3]);
            }
        }
    }

    // ---- mirrored store via smem transpose (skip diagonal) ----
    if (br != bc) {
        float* Tf = reinterpret_cast<float*>(smem_raw);   // [128 cols][68 rows]
#pragma unroll
        for (int h = 0; h < 2; ++h) {
            __syncthreads();
            if (warp_m == h) {
#pragma unroll
                for (int mi = 0; mi < 4; mi++) {
                    const int rl = mi * 16 + (lane >> 2);
#pragma unroll
                    for (int ni = 0; ni < 4; ni++) {
                        const int cl = warp_n * 32 + ni * 8 + (lane & 3) * 2;
                        Tf[cl * 68 + rl]           = acc[mi][ni][0];
                        Tf[(cl + 1) * 68 + rl]     = acc[mi][ni][1];
                        Tf[cl * 68 + rl + 8]       = acc[mi][ni][2];
                        Tf[(cl + 1) * 68 + rl + 8] = acc[mi][ni][3];
                    }
                }
            }
            __syncthreads();
#pragma unroll
            for (int p = 0; p < 8; ++p) {
                const int idx = tid + p * 256;
                const int i = idx >> 4;
                const int j = idx & 15;
                const int grow2 = bc * 128 + i;
                if (grow2 < N_ROWS) {
                    long base = (long)grow2 * LDOUT + br * 128 + h * 64 + j * 4;
                    float4 v;
                    v.x = Tf[i * 68 + j * 4 + 0];
                    v.y = Tf[i * 68 + j * 4 + 1];
                    v.z = Tf[i * 68 + j * 4 + 2];
                    v.w = Tf[i * 68 + j * 4 + 3];
                    *reinterpret_cast<float4*>(&out[base]) = v;
                }
            }
        }
    }
}

// ---- fused select: 512 threads, parallel scans, SERIAL-fmaf rescore --------
__device__ __forceinline__ unsigned fkey(float f)
{
    unsigned u = __float_as_uint(f);
    return (u & 0x80000000u) ? ~u : (u | 0x80000000u);
}
__device__ __forceinline__ float kinv(unsigned key)
{
    unsigned u = (key & 0x80000000u) ? (key & 0x7fffffffu) : ~key;
    return __uint_as_float(u);
}

__global__ void __launch_bounds__(STH) select_kernel(float* __restrict__ out,
                                                     const int* __restrict__ kp)
{
    __shared__ unsigned hist[4096];        // -> cidx after refine pick
    __shared__ unsigned suf[256];          // chunk suffix sums
    __shared__ float erow[DIM];
    __shared__ unsigned skey[CAP];         // -> cval after prune
    __shared__ int      sidx[CAP];
    __shared__ int stageCnt, candCnt;
    __shared__ unsigned sh_b1, sh_r1, sh_b2;

    int*   cidx = reinterpret_cast<int*>(hist);
    float* cval = reinterpret_cast<float*>(skey);

    const int row = blockIdx.x;
    const int tid = threadIdx.x;
    float* rowp = out + (long)row * LDOUT;
    const float4* r4 = reinterpret_cast<const float4*>(rowp);
    const unsigned K1 = (unsigned)(kp[0] + 1);

    for (int i = tid; i < 4096; i += STH) hist[i] = 0;
    if (tid == 0) { stageCnt = 0; candCnt = 0; }
    if (tid < DIM) erow[tid] = g_e[(long)row * DIM + tid];
    __syncthreads();

    // ---- sweep 1: top-12-bit histogram (DRAM read) ----
    for (int i = tid; i < LDOUT / 4; i += STH) {
        float4 v = r4[i];
        atomicAdd(&hist[fkey(v.x) >> 20], 1u);
        atomicAdd(&hist[fkey(v.y) >> 20], 1u);
        atomicAdd(&hist[fkey(v.z) >> 20], 1u);
        atomicAdd(&hist[fkey(v.w) >> 20], 1u);
    }
    __syncthreads();

    // chunk sums (16 bins/chunk) + parallel suffix scan + crossing pick
    if (tid < 256) {
        unsigned s = 0;
#pragma unroll
        for (int b = 0; b < 16; b++) s += hist[tid * 16 + b];
        suf[tid] = s;
    }
    __syncthreads();
#pragma unroll
    for (int st = 1; st < 256; st <<= 1) {
        unsigned add = 0;
        if (tid < 256 && tid + st < 256) add = suf[tid + st];
        __syncthreads();
        if (tid < 256) suf[tid] += add;
        __syncthreads();
    }
    if (tid < 256) {
        unsigned below = (tid < 255) ? suf[tid + 1] : 0u;    // count above this chunk
        if (suf[tid] >= K1 && below < K1) {                  // unique crossing chunk
            unsigned cum = below;
            for (int b = tid * 16 + 15; b >= tid * 16; --b) {
                unsigned hh = hist[b];
                if (cum + hh >= K1) { sh_b1 = (unsigned)b; sh_r1 = K1 - cum; break; }
                cum += hh;
            }
        }
    }
    __syncthreads();
    const unsigned b1 = sh_b1, r1 = sh_r1;

    // zero refine histogram before sweep 2
    for (int i = tid; i < 4096; i += STH) hist[i] = 0;
    __syncthreads();

    // pre-threshold: anything surviving final Tm has key >= Kpre
    const unsigned Kpre = fkey(kinv(b1 << 20) - DELTA);

    // ---- sweep 2: refine hist + stage candidates + zero the row (L2) ----
    const float4 z = make_float4(0.f, 0.f, 0.f, 0.f);
    for (int i = tid; i < LDOUT / 4; i += STH) {
        float4 v = r4[i];
        const float* pv = &v.x;
#pragma unroll
        for (int q = 0; q < 4; ++q) {
            unsigned u = fkey(pv[q]);
            if (u >= Kpre) {
                int p = atomicAdd(&stageCnt, 1);
                if (p < CAP) { skey[p] = u; sidx[p] = i * 4 + q; }
            }
            if ((u >> 20) == b1) atomicAdd(&hist[(u >> 8) & 0xFFFu], 1u);
        }
        reinterpret_cast<float4*>(rowp)[i] = z;
    }
    __syncthreads();

    if (tid < 256) {
        unsigned s = 0;
#pragma unroll
        for (int b = 0; b < 16; b++) s += hist[tid * 16 + b];
        suf[tid] = s;
    }
    __syncthreads();
#pragma unroll
    for (int st = 1; st < 256; st <<= 1) {
        unsigned add = 0;
        if (tid < 256 && tid + st < 256) add = suf[tid + st];
        __syncthreads();
        if (tid < 256) suf[tid] += add;
        __syncthreads();
    }
    if (tid == 0 && suf[0] < r1) sh_b2 = 0;   // safety (shouldn't happen)
    if (tid < 256) {
        unsigned below = (tid < 255) ? suf[tid + 1] : 0u;
        if (suf[tid] >= r1 && below < r1) {
            unsigned cum = below;
            for (int b = tid * 16 + 15; b >= tid * 16; --b) {
                unsigned hh = hist[b];
                if (cum + hh >= r1) { sh_b2 = (unsigned)b; break; }
                cum += hh;
            }
        }
    }
    __syncthreads();

    // final threshold with margin
    const unsigned F = (b1 << 20) | (sh_b2 << 8);
    const unsigned Tm = fkey(kinv(F) - DELTA);

    // ---- prune staged -> final candidate list (cidx aliases hist) ----
    const int ns = stageCnt < CAP ? stageCnt : CAP;
    for (int c = tid; c < ns; c += STH) {
        if (skey[c] >= Tm) {
            int p = atomicAdd(&candCnt, 1);
            if (p < CAND_MAX) cidx[p] = sidx[c];
        }
    }
    __syncthreads();
    const int n = candCnt < CAND_MAX ? candCnt : CAND_MAX;

    // ---- exact fp32 rescore: serial fmaf chain (order is load-bearing) ----
    for (int c = tid; c < n; c += STH) {
        const float* ec = &g_e[(long)cidx[c] * DIM];
        float a = 0.f;
#pragma unroll 8
        for (int k = 0; k < DIM; ++k) a = fmaf(erow[k], ec[k], a);
        cval[c] = a;
    }
    __syncthreads();

    // ---- rank (val desc, idx asc) and scatter kept entries ----
    for (int c = tid; c < n; c += STH) {
        float v = cval[c];
        int  id = cidx[c];
        int rank = 0;
        for (int o = 0; o < n; ++o) {
            float vo = cval[o];
            rank += (vo > v) || (vo == v && cidx[o] < id);
        }
        if (rank < (int)K1) rowp[id] = fmaxf(v, 0.f);
    }
}

// ---------------- launch ----------------------------------------------------
extern "C" void kernel_launch(void* const* d_in, const int* in_sizes, int n_in,
                              void* d_out, int out_size)
{
    const float* h  = (const float*)d_in[0];
    const float* W1 = (const float*)d_in[1];
    const float* b1 = (const float*)d_in[2];
    const float* W2 = (const float*)d_in[3];
    const float* b2 = (const float*)d_in[4];
    const int*   kp = (const int*)  d_in[5];
    float* out = (float*)d_out;

    mlp1_kernel<<<dim3(NB, 2), 256>>>(h, W1, b1);
    mlp2_kernel<<<dim3(NB, 2), 256>>>(W2, b2);
    normalize_kernel<<<NPAD, 256>>>();
    adj_hmma_kernel<<<dim3(NB, NB), 256>>>(out);
    select_kernel<<<N_ROWS, STH>>>(out, kp);
}